// round 1
// baseline (speedup 1.0000x reference)
#include <cuda_runtime.h>
#include <math.h>
#include <stdint.h>

#define Bn 8
#define Tn 2048
#define Cn 768
#define Hn 12
#define KSEL 1024
#define DFF 3072
#define BT (Bn*Tn)      /* 16384 */
#define BKn (Bn*KSEL)   /* 8192 */
#define G3C (3*Cn)      /* 2304 */

// ---------------- scratch (device globals; no allocation allowed) ----------
__device__ float g_xi[(size_t)BT*G3C];
__device__ float g_hrnn[(size_t)BT*Cn];
__device__ float g_hstate[Bn*Cn];
__device__ float g_energy[BT];
__device__ int   g_idx[BKn];
__device__ int   g_selmap[BT];
__device__ float g_xsel[(size_t)BKn*Cn];
__device__ float g_gsel[BKn];
__device__ float g_qkv[(size_t)BKn*G3C];
__device__ float g_y[(size_t)BKn*Cn];
__device__ float g_weighted[(size_t)BKn*Cn];
__device__ float g_hln[(size_t)BT*Cn];
__device__ float g_mid[(size_t)BT*DFF];
__device__ unsigned g_bar;
__device__ int g_active;

// ---------------- init ------------------------------------------------------
__global__ void init_kernel() {
    int tid = blockIdx.x * blockDim.x + threadIdx.x;
    if (tid == 0) { g_bar = 0u; g_active = 0; }
    for (int i = tid; i < Bn*Cn; i += gridDim.x*blockDim.x) g_hstate[i] = 0.f;
    for (int i = tid; i < BT;    i += gridDim.x*blockDim.x) g_selmap[i] = -1;
}

// ---------------- SGEMM: C[M,N] = A[M,K] @ W[N,K]^T + bias, epilogues -------
// EP: 0 none, 1 gelu(exact erf), 2 row-scale(extra[m]), 3 residual(extra[m*N+n])
template<int EP>
__global__ __launch_bounds__(256)
void gemm_kernel(const float* __restrict__ A, const float* __restrict__ W,
                 const float* __restrict__ bias, const float* __restrict__ extra,
                 float* __restrict__ Cc, int M, int N, int K) {
    __shared__ float As[8][128];
    __shared__ float Bs[8][128];
    int tid = threadIdx.x;
    int m0 = blockIdx.y * 128, n0 = blockIdx.x * 128;
    int tr = tid >> 4, tc = tid & 15;
    float acc[8][8];
#pragma unroll
    for (int i = 0; i < 8; i++)
#pragma unroll
        for (int j = 0; j < 8; j++) acc[i][j] = 0.f;

    int lr = tid >> 1;
    int lc = (tid & 1) * 4;
    const float* Ap = A + (size_t)(m0 + lr) * K + lc;
    const float* Wp = W + (size_t)(n0 + lr) * K + lc;

    for (int kt = 0; kt < K; kt += 8) {
        float4 av = *(const float4*)(Ap + kt);
        float4 wv = *(const float4*)(Wp + kt);
        As[lc + 0][lr] = av.x; As[lc + 1][lr] = av.y;
        As[lc + 2][lr] = av.z; As[lc + 3][lr] = av.w;
        Bs[lc + 0][lr] = wv.x; Bs[lc + 1][lr] = wv.y;
        Bs[lc + 2][lr] = wv.z; Bs[lc + 3][lr] = wv.w;
        __syncthreads();
#pragma unroll
        for (int kk = 0; kk < 8; kk++) {
            float a[8], b[8];
            *(float4*)(a)     = *(const float4*)&As[kk][tr*8];
            *(float4*)(a + 4) = *(const float4*)&As[kk][tr*8 + 4];
            *(float4*)(b)     = *(const float4*)&Bs[kk][tc*8];
            *(float4*)(b + 4) = *(const float4*)&Bs[kk][tc*8 + 4];
#pragma unroll
            for (int i = 0; i < 8; i++)
#pragma unroll
                for (int j = 0; j < 8; j++) acc[i][j] += a[i] * b[j];
        }
        __syncthreads();
    }

#pragma unroll
    for (int i = 0; i < 8; i++) {
        int m = m0 + tr*8 + i;
        float rs = (EP == 2) ? extra[m] : 0.f;
#pragma unroll
        for (int j = 0; j < 8; j++) {
            int n = n0 + tc*8 + j;
            float v = acc[i][j] + bias[n];
            if (EP == 1) v = 0.5f * v * (1.f + erff(v * 0.70710678118654752f));
            if (EP == 2) v *= rs;
            if (EP == 3) v += extra[(size_t)m * N + n];
            Cc[(size_t)m * N + n] = v;
        }
    }
}

// ---------------- GRU persistent kernel -------------------------------------
#define NCTA_GRU 128
#define CHB 6   /* channels per CTA: 128*6 = 768 */
__global__ __launch_bounds__(192, 1)
void gru_kernel(const float* __restrict__ xi, const float* __restrict__ Whh,
                const float* __restrict__ bhh) {
    __shared__ float hs[Bn][Cn];
    __shared__ float gbuf[CHB][3][Bn];
    int tid = threadIdx.x, w = tid >> 5, lane = tid & 31;
    int c0 = blockIdx.x * CHB;
    int ch = c0 + w;  // warp's channel (6 warps)

    // recurrent weights resident in registers: 3 gates x 6 float4 = 72 floats
    float4 wreg[3][6];
#pragma unroll
    for (int g = 0; g < 3; g++)
#pragma unroll
        for (int j = 0; j < 6; j++)
            wreg[g][j] = __ldg((const float4*)(Whh + (size_t)(g*Cn + ch) * Cn) + (j*32 + lane));

    bool is_comb = tid < (Bn * CHB);
    int bcomb = 0, ccomb = 0;
    float bhr = 0.f, bhz = 0.f, bhn = 0.f;
    if (is_comb) {
        bcomb = tid / CHB; ccomb = c0 + tid % CHB;
        bhr = __ldg(bhh + ccomb);
        bhz = __ldg(bhh + Cn + ccomb);
        bhn = __ldg(bhh + 2*Cn + ccomb);
    }

    unsigned target = NCTA_GRU;
    for (int t = 0; t < Tn; t++) {
        // stage h state (L1-bypass: other CTAs wrote it last step)
        const float4* hp = (const float4*)g_hstate;
        float4* hd = (float4*)&hs[0][0];
#pragma unroll
        for (int i = 0; i < 8; i++) hd[tid + i*192] = __ldcg(hp + tid + i*192);

        float xr = 0.f, xz = 0.f, xn = 0.f;
        if (is_comb) {
            const float* xrow = xi + ((size_t)bcomb*Tn + t) * G3C + ccomb;
            xr = __ldg(xrow); xz = __ldg(xrow + Cn); xn = __ldg(xrow + 2*Cn);
        }
        __syncthreads();

        float acc[3][Bn];
#pragma unroll
        for (int g = 0; g < 3; g++)
#pragma unroll
            for (int b = 0; b < Bn; b++) acc[g][b] = 0.f;

#pragma unroll
        for (int j = 0; j < 6; j++) {
            float4 h4[Bn];
#pragma unroll
            for (int b = 0; b < Bn; b++)
                h4[b] = ((const float4*)&hs[b][0])[j*32 + lane];
#pragma unroll
            for (int b = 0; b < Bn; b++) {
#pragma unroll
                for (int g = 0; g < 3; g++) {
                    acc[g][b] += wreg[g][j].x * h4[b].x + wreg[g][j].y * h4[b].y
                               + wreg[g][j].z * h4[b].z + wreg[g][j].w * h4[b].w;
                }
            }
        }
        // lane reduce
#pragma unroll
        for (int g = 0; g < 3; g++)
#pragma unroll
            for (int b = 0; b < Bn; b++) {
#pragma unroll
                for (int off = 16; off > 0; off >>= 1)
                    acc[g][b] += __shfl_xor_sync(0xffffffffu, acc[g][b], off);
            }
        if (lane == 0) {
#pragma unroll
            for (int g = 0; g < 3; g++)
#pragma unroll
                for (int b = 0; b < Bn; b++) gbuf[w][g][b] = acc[g][b];
        }
        __syncthreads();

        if (is_comb) {
            int cc = tid % CHB;
            float hr = gbuf[cc][0][bcomb] + bhr;
            float hz = gbuf[cc][1][bcomb] + bhz;
            float hn = gbuf[cc][2][bcomb] + bhn;
            float r = 1.f / (1.f + expf(-(xr + hr)));
            float z = 1.f / (1.f + expf(-(xz + hz)));
            float n = tanhf(xn + r * hn);
            float hold = hs[bcomb][ccomb];
            float hnew = (1.f - z) * n + z * hold;
            g_hstate[bcomb*Cn + ccomb] = hnew;
            g_hrnn[((size_t)bcomb*Tn + t) * Cn + ccomb] = hnew;
            __threadfence();
        }
        __syncthreads();
        if (tid == 0) {
            atomicAdd(&g_bar, 1u);
            volatile unsigned* p = &g_bar;
            while (*p < target) __nanosleep(64);
        }
        target += NCTA_GRU;
        __syncthreads();
    }
}

// ---------------- gate MLP / energy -----------------------------------------
__global__ __launch_bounds__(128)
void energy_kernel(const float* __restrict__ gw1, const float* __restrict__ gb1,
                   const float* __restrict__ gw2, const float* __restrict__ gb2,
                   float* __restrict__ out_energy) {
    int tok = blockIdx.x;
    int tid = threadIdx.x, w = tid >> 5, lane = tid & 31;
    __shared__ float dots[32];
    const float* h = g_hrnn + (size_t)tok * Cn;
#pragma unroll
    for (int jj = 0; jj < 8; jj++) {
        int j = w * 8 + jj;
        const float* wr = gw1 + (size_t)j * Cn;
        float p = 0.f;
        for (int k = lane; k < Cn; k += 32) p += h[k] * wr[k];
#pragma unroll
        for (int off = 16; off > 0; off >>= 1) p += __shfl_xor_sync(0xffffffffu, p, off);
        if (lane == 0) dots[j] = p;
    }
    __syncthreads();
    if (tid == 0) {
        float a = gb2[0];
#pragma unroll
        for (int j = 0; j < 32; j++) a += tanhf(dots[j] + gb1[j]) * gw2[j];
        float e = 1.f / (1.f + expf(-a));
        g_energy[tok] = e;
        out_energy[tok] = e;
        if (e > 0.5f) atomicAdd(&g_active, 1);
    }
}

// ---------------- exact top-k via bitonic sort -------------------------------
__global__ __launch_bounds__(1024)
void topk_kernel() {
    __shared__ unsigned long long keys[Tn];
    __shared__ int sel[KSEL];
    int b = blockIdx.x, tid = threadIdx.x;
    for (int e = tid; e < Tn; e += 1024) {
        unsigned u = __float_as_uint(g_energy[b*Tn + e]);
        u = (u & 0x80000000u) ? ~u : (u | 0x80000000u);
        keys[e] = ((unsigned long long)u << 32) | (unsigned)(Tn - 1 - e);
    }
    __syncthreads();
    // descending sort (ties -> lower index first)
    for (int k = 2; k <= Tn; k <<= 1)
        for (int j = k >> 1; j > 0; j >>= 1) {
            int p = tid;
            int e = ((p & ~(j - 1)) << 1) | (p & (j - 1));
            int f = e | j;
            unsigned long long a = keys[e], c = keys[f];
            bool up = ((e & k) == 0);
            bool sw = up ? (a < c) : (a > c);
            if (sw) { keys[e] = c; keys[f] = a; }
            __syncthreads();
        }
    if (tid < KSEL) sel[tid] = Tn - 1 - (int)(keys[tid] & 0xffffffffull);
    __syncthreads();
    // ascending sort of selected indices
    for (int k = 2; k <= KSEL; k <<= 1)
        for (int j = k >> 1; j > 0; j >>= 1) {
            if (tid < KSEL/2) {
                int p = tid;
                int e = ((p & ~(j - 1)) << 1) | (p & (j - 1));
                int f = e | j;
                int a = sel[e], c = sel[f];
                bool up = ((e & k) == 0);
                bool sw = up ? (a > c) : (a < c);
                if (sw) { sel[e] = c; sel[f] = a; }
            }
            __syncthreads();
        }
    if (tid < KSEL) g_idx[b*KSEL + tid] = sel[tid];
}

// ---------------- gather selected tokens -------------------------------------
__global__ __launch_bounds__(192)
void gather_kernel() {
    int bk = blockIdx.x;
    int b = bk / KSEL;
    int t = g_idx[bk];
    if (threadIdx.x == 0) {
        g_gsel[bk] = g_energy[b*Tn + t];
        g_selmap[b*Tn + t] = bk % KSEL;
    }
    const float4* src = (const float4*)(g_hrnn + ((size_t)b*Tn + t) * Cn);
    float4* dst = (float4*)(g_xsel + (size_t)bk * Cn);
    dst[threadIdx.x] = src[threadIdx.x];
}

// ---------------- flash attention (causal, hd=64, Klen=1024) -----------------
__global__ __launch_bounds__(256)
void attn_kernel() {
    extern __shared__ float sm[];
    float* Qs = sm;                 // 64 x 65
    float* Ks = Qs + 64*65;         // 64 x 65
    float* Ps = Ks + 64*65;         // 64 x 65
    float* Vs = Ps + 64*65;         // 64 x 64
    int qt = blockIdx.x, bh = blockIdx.y;
    int b = bh / Hn, h = bh % Hn;
    int tid = threadIdx.x, tr = tid >> 4, tc = tid & 15;
    int q0 = qt * 64;
    const float* base = g_qkv + (size_t)b * KSEL * G3C;

    for (int i = tid; i < 1024; i += 256) {
        int r = i >> 4, d4 = i & 15;
        float4 v = __ldg((const float4*)(base + (size_t)(q0 + r)*G3C + h*64) + d4);
        Qs[r*65 + d4*4 + 0] = v.x; Qs[r*65 + d4*4 + 1] = v.y;
        Qs[r*65 + d4*4 + 2] = v.z; Qs[r*65 + d4*4 + 3] = v.w;
    }

    float o[4][4], m[4], l[4];
#pragma unroll
    for (int i = 0; i < 4; i++) {
        m[i] = -1e30f; l[i] = 0.f;
#pragma unroll
        for (int j = 0; j < 4; j++) o[i][j] = 0.f;
    }

    for (int kt = 0; kt <= qt; kt++) {
        int k0 = kt * 64;
        for (int i = tid; i < 1024; i += 256) {
            int c = i >> 4, d4 = i & 15;
            float4 kv = __ldg((const float4*)(base + (size_t)(k0 + c)*G3C + Cn + h*64) + d4);
            Ks[c*65 + d4*4 + 0] = kv.x; Ks[c*65 + d4*4 + 1] = kv.y;
            Ks[c*65 + d4*4 + 2] = kv.z; Ks[c*65 + d4*4 + 3] = kv.w;
            float4 vv = __ldg((const float4*)(base + (size_t)(k0 + c)*G3C + 2*Cn + h*64) + d4);
            ((float4*)(Vs + c*64))[d4] = vv;
        }
        __syncthreads();

        float s[4][4];
#pragma unroll
        for (int i = 0; i < 4; i++)
#pragma unroll
            for (int j = 0; j < 4; j++) s[i][j] = 0.f;
        for (int kk = 0; kk < 64; kk++) {
            float a[4], bb[4];
#pragma unroll
            for (int i = 0; i < 4; i++) a[i] = Qs[(tr*4 + i)*65 + kk];
#pragma unroll
            for (int j = 0; j < 4; j++) bb[j] = Ks[(tc*4 + j)*65 + kk];
#pragma unroll
            for (int i = 0; i < 4; i++)
#pragma unroll
                for (int j = 0; j < 4; j++) s[i][j] += a[i] * bb[j];
        }
#pragma unroll
        for (int i = 0; i < 4; i++)
#pragma unroll
            for (int j = 0; j < 4; j++) s[i][j] *= 0.125f;
        if (kt == qt) {
#pragma unroll
            for (int i = 0; i < 4; i++)
#pragma unroll
                for (int j = 0; j < 4; j++)
                    if (k0 + tc*4 + j > q0 + tr*4 + i) s[i][j] = -1e30f;
        }
        // online softmax
#pragma unroll
        for (int i = 0; i < 4; i++) {
            float rm = s[i][0];
#pragma unroll
            for (int j = 1; j < 4; j++) rm = fmaxf(rm, s[i][j]);
#pragma unroll
            for (int off = 8; off > 0; off >>= 1)
                rm = fmaxf(rm, __shfl_xor_sync(0xffffffffu, rm, off));
            float mn = fmaxf(m[i], rm);
            float alpha = expf(m[i] - mn);
            float rs = 0.f;
#pragma unroll
            for (int j = 0; j < 4; j++) {
                s[i][j] = expf(s[i][j] - mn);
                rs += s[i][j];
            }
#pragma unroll
            for (int off = 8; off > 0; off >>= 1)
                rs += __shfl_xor_sync(0xffffffffu, rs, off);
            l[i] = l[i] * alpha + rs;
            m[i] = mn;
#pragma unroll
            for (int j = 0; j < 4; j++) o[i][j] *= alpha;
#pragma unroll
            for (int j = 0; j < 4; j++) Ps[(tr*4 + i)*65 + tc*4 + j] = s[i][j];
        }
        __syncthreads();
        for (int c = 0; c < 64; c++) {
            float pv[4], vv[4];
#pragma unroll
            for (int i = 0; i < 4; i++) pv[i] = Ps[(tr*4 + i)*65 + c];
#pragma unroll
            for (int j = 0; j < 4; j++) vv[j] = Vs[c*64 + tc*4 + j];
#pragma unroll
            for (int i = 0; i < 4; i++)
#pragma unroll
                for (int j = 0; j < 4; j++) o[i][j] += pv[i] * vv[j];
        }
        __syncthreads();
    }
#pragma unroll
    for (int i = 0; i < 4; i++) {
        float inv = 1.f / l[i];
        int row = b * KSEL + q0 + tr*4 + i;
#pragma unroll
        for (int j = 0; j < 4; j++)
            g_y[(size_t)row * Cn + h*64 + tc*4 + j] = o[i][j] * inv;
    }
}

// ---------------- LayerNorm with fused scatter-add ---------------------------
__global__ __launch_bounds__(256)
void ln_kernel(const float* __restrict__ g, const float* __restrict__ bb) {
    __shared__ float xrow[Cn];
    __shared__ float rbuf[16];
    int tok = blockIdx.x, tid = threadIdx.x;
    int b = tok >> 11;
    int sel = g_selmap[tok];
    float s = 0.f, s2 = 0.f;
    for (int c = tid; c < Cn; c += 256) {
        float v = g_hrnn[(size_t)tok*Cn + c];
        if (sel >= 0) v += g_weighted[((size_t)(b*KSEL + sel))*Cn + c];
        xrow[c] = v; s += v; s2 += v*v;
    }
#pragma unroll
    for (int off = 16; off > 0; off >>= 1) {
        s  += __shfl_xor_sync(0xffffffffu, s, off);
        s2 += __shfl_xor_sync(0xffffffffu, s2, off);
    }
    int w = tid >> 5;
    if ((tid & 31) == 0) { rbuf[w] = s; rbuf[8 + w] = s2; }
    __syncthreads();
    if (tid == 0) {
        float S = 0.f, S2 = 0.f;
        for (int i = 0; i < 8; i++) { S += rbuf[i]; S2 += rbuf[8 + i]; }
        float mu = S / (float)Cn;
        float var = S2 / (float)Cn - mu*mu;
        rbuf[0] = mu; rbuf[1] = rsqrtf(var + 1e-5f);
    }
    __syncthreads();
    float mu = rbuf[0], inv = rbuf[1];
    for (int c = tid; c < Cn; c += 256)
        g_hln[(size_t)tok*Cn + c] = (xrow[c] - mu) * inv * g[c] + bb[c];
}

// ---------------- finalize ----------------------------------------------------
__global__ void finalize_kernel(float* out) {
    out[(size_t)BT*Cn + BT] = (float)g_active;
}

// ---------------- launcher ----------------------------------------------------
extern "C" void kernel_launch(void* const* d_in, const int* in_sizes, int n_in,
                              void* d_out, int out_size) {
    const float* x      = (const float*)d_in[0];
    const float* W_ih   = (const float*)d_in[1];
    const float* W_hh   = (const float*)d_in[2];
    const float* b_ih   = (const float*)d_in[3];
    const float* b_hh   = (const float*)d_in[4];
    const float* gate_w1= (const float*)d_in[5];
    const float* gate_b1= (const float*)d_in[6];
    const float* gate_w2= (const float*)d_in[7];
    const float* gate_b2= (const float*)d_in[8];
    const float* qkv_w  = (const float*)d_in[9];
    const float* qkv_b  = (const float*)d_in[10];
    const float* proj_w = (const float*)d_in[11];
    const float* proj_b = (const float*)d_in[12];
    const float* ln_g   = (const float*)d_in[13];
    const float* ln_b   = (const float*)d_in[14];
    const float* ffn_w1 = (const float*)d_in[15];
    const float* ffn_b1 = (const float*)d_in[16];
    const float* ffn_w2 = (const float*)d_in[17];
    const float* ffn_b2 = (const float*)d_in[18];
    float* out = (float*)d_out;

    // device-global scratch addresses
    float *p_xi, *p_xsel, *p_qkv, *p_y, *p_weighted, *p_hln, *p_mid, *p_energy_out;
    cudaGetSymbolAddress((void**)&p_xi,       g_xi);
    cudaGetSymbolAddress((void**)&p_xsel,     g_xsel);
    cudaGetSymbolAddress((void**)&p_qkv,      g_qkv);
    cudaGetSymbolAddress((void**)&p_y,        g_y);
    cudaGetSymbolAddress((void**)&p_weighted, g_weighted);
    cudaGetSymbolAddress((void**)&p_hln,      g_hln);
    cudaGetSymbolAddress((void**)&p_mid,      g_mid);
    float* p_gsel; cudaGetSymbolAddress((void**)&p_gsel, g_gsel);
    p_energy_out = out + (size_t)BT*Cn;

    const int ATTN_SMEM = (3*64*65 + 64*64) * 4;
    cudaFuncSetAttribute(attn_kernel, cudaFuncAttributeMaxDynamicSharedMemorySize, ATTN_SMEM);

    // 0) init scratch state
    init_kernel<<<64, 256>>>();

    // 1) xi = x @ W_ih^T + b_ih   [16384, 2304]
    gemm_kernel<0><<<dim3(G3C/128, BT/128), 256>>>(x, W_ih, b_ih, nullptr, p_xi, BT, G3C, Cn);

    // 2) GRU scan (persistent, global barrier per step)
    gru_kernel<<<NCTA_GRU, 192>>>(p_xi, W_hh, b_hh);

    // 3) gate MLP energy (+ writes energy output + active count)
    energy_kernel<<<BT, 128>>>(gate_w1, gate_b1, gate_w2, gate_b2, p_energy_out);

    // 4) exact top-k + ascending index sort
    topk_kernel<<<Bn, 1024>>>();

    // 5) gather selected tokens; build inverse map + gate values
    gather_kernel<<<BKn, 192>>>();

    // 6) qkv = x_sel @ qkv_w^T + qkv_b  [8192, 2304]
    gemm_kernel<0><<<dim3(G3C/128, BKn/128), 256>>>(p_xsel, qkv_w, qkv_b, nullptr, p_qkv, BKn, G3C, Cn);

    // 7) causal flash attention
    attn_kernel<<<dim3(KSEL/64, Bn*Hn), 256, ATTN_SMEM>>>();

    // 8) weighted = (y @ proj_w^T + proj_b) * g_sel  [8192, 768]
    gemm_kernel<2><<<dim3(Cn/128, BKn/128), 256>>>(p_y, proj_w, proj_b, p_gsel, p_weighted, BKn, Cn, Cn);

    // 9) LayerNorm(h_rnn + scatter(weighted))
    ln_kernel<<<BT, 256>>>(ln_g, ln_b);

    // 10) mid = gelu(h_ln @ ffn_w1^T + ffn_b1)  [16384, 3072]
    gemm_kernel<1><<<dim3(DFF/128, BT/128), 256>>>(p_hln, ffn_w1, ffn_b1, nullptr, p_mid, BT, DFF, Cn);

    // 11) out_h = h_ln + mid @ ffn_w2^T + ffn_b2  -> d_out[0 : BT*C]
    gemm_kernel<3><<<dim3(Cn/128, BT/128), 256>>>(p_mid, ffn_w2, ffn_b2, p_hln, out, BT, Cn, DFF);

    // 12) active count
    finalize_kernel<<<1, 1>>>(out);

    (void)in_sizes; (void)n_in; (void)out_size;
}

// round 2
// speedup vs baseline: 1.0397x; 1.0397x over previous
#include <cuda_runtime.h>
#include <math.h>
#include <stdint.h>

#define Bn 8
#define Tn 2048
#define Cn 768
#define Hn 12
#define KSEL 1024
#define DFF 3072
#define BT (Bn*Tn)      /* 16384 */
#define BKn (Bn*KSEL)   /* 8192 */
#define G3C (3*Cn)      /* 2304 */

typedef unsigned long long ull;

// ---------------- f32x2 packed helpers (FFMA2 path, sm_100+) ----------------
__device__ __forceinline__ ull pk2(float x, float y) {
    ull r; asm("mov.b64 %0, {%1, %2};" : "=l"(r) : "f"(x), "f"(y)); return r;
}
__device__ __forceinline__ ull dup2(float x) { return pk2(x, x); }
__device__ __forceinline__ void fma2(ull &acc, ull a, ull b) {
    asm("fma.rn.f32x2 %0, %1, %2, %0;" : "+l"(acc) : "l"(a), "l"(b));
}
__device__ __forceinline__ ull mul2(ull a, ull b) {
    ull r; asm("mul.rn.f32x2 %0, %1, %2;" : "=l"(r) : "l"(a), "l"(b)); return r;
}
__device__ __forceinline__ float2 upk2(ull v) {
    float2 r; asm("mov.b64 {%0, %1}, %2;" : "=f"(r.x), "=f"(r.y) : "l"(v)); return r;
}

// ---------------- scratch (device globals; no allocation allowed) ----------
__device__ float g_xi[(size_t)BT*G3C];
__device__ float g_hrnn[(size_t)BT*Cn];
__device__ float g_hstate[Bn*Cn];
__device__ float g_energy[BT];
__device__ int   g_idx[BKn];
__device__ int   g_selmap[BT];
__device__ float g_xsel[(size_t)BKn*Cn];
__device__ float g_gsel[BKn];
__device__ float g_qkv[(size_t)BKn*G3C];
__device__ float g_y[(size_t)BKn*Cn];
__device__ float g_weighted[(size_t)BKn*Cn];
__device__ float g_hln[(size_t)BT*Cn];
__device__ float g_mid[(size_t)BT*DFF];
__device__ unsigned g_bar;
__device__ int g_active;

// ---------------- init ------------------------------------------------------
__global__ void init_kernel() {
    int tid = blockIdx.x * blockDim.x + threadIdx.x;
    if (tid == 0) { g_bar = 0u; g_active = 0; }
    for (int i = tid; i < Bn*Cn; i += gridDim.x*blockDim.x) g_hstate[i] = 0.f;
    for (int i = tid; i < BT;    i += gridDim.x*blockDim.x) g_selmap[i] = -1;
}

// ---------------- SGEMM (FFMA2 + double buffer) ------------------------------
// C[M,N] = A[M,K] @ W[N,K]^T + bias
// EP: 0 none, 1 gelu(exact erf), 2 row-scale(extra[m]), 3 residual(extra[m*N+n])
template<int EP>
__global__ __launch_bounds__(256, 2)
void gemm_kernel(const float* __restrict__ A, const float* __restrict__ W,
                 const float* __restrict__ bias, const float* __restrict__ extra,
                 float* __restrict__ Cc, int M, int N, int K) {
    __shared__ float As[2][8][128];
    __shared__ float Bs[2][8][128];
    int tid = threadIdx.x;
    int m0 = blockIdx.y * 128, n0 = blockIdx.x * 128;
    int tr = tid >> 4, tc = tid & 15;

    ull acc[8][4];
#pragma unroll
    for (int i = 0; i < 8; i++)
#pragma unroll
        for (int j = 0; j < 4; j++) acc[i][j] = 0ull;  // {0.f,0.f}

    int lr = tid >> 1;
    int lc = (tid & 1) * 4;
    const float* Ap = A + (size_t)(m0 + lr) * K + lc;
    const float* Wp = W + (size_t)(n0 + lr) * K + lc;

    // prologue: tile 0 into buffer 0
    {
        float4 av = *(const float4*)(Ap);
        float4 wv = *(const float4*)(Wp);
        As[0][lc + 0][lr] = av.x; As[0][lc + 1][lr] = av.y;
        As[0][lc + 2][lr] = av.z; As[0][lc + 3][lr] = av.w;
        Bs[0][lc + 0][lr] = wv.x; Bs[0][lc + 1][lr] = wv.y;
        Bs[0][lc + 2][lr] = wv.z; Bs[0][lc + 3][lr] = wv.w;
    }
    __syncthreads();

    int buf = 0;
    for (int kt = 8; kt <= K; kt += 8) {
        // prefetch next tile into registers (overlaps with compute)
        float4 av, wv;
        bool more = (kt < K);
        if (more) {
            av = *(const float4*)(Ap + kt);
            wv = *(const float4*)(Wp + kt);
        }
#pragma unroll
        for (int kk = 0; kk < 8; kk++) {
            float4 a0 = *(const float4*)&As[buf][kk][tr*8];
            float4 a1 = *(const float4*)&As[buf][kk][tr*8 + 4];
            float4 b0 = *(const float4*)&Bs[buf][kk][tc*8];
            float4 b1 = *(const float4*)&Bs[buf][kk][tc*8 + 4];
            ull bp[4] = { pk2(b0.x,b0.y), pk2(b0.z,b0.w),
                          pk2(b1.x,b1.y), pk2(b1.z,b1.w) };
            ull ad[8] = { dup2(a0.x), dup2(a0.y), dup2(a0.z), dup2(a0.w),
                          dup2(a1.x), dup2(a1.y), dup2(a1.z), dup2(a1.w) };
#pragma unroll
            for (int i = 0; i < 8; i++)
#pragma unroll
                for (int jp = 0; jp < 4; jp++) fma2(acc[i][jp], ad[i], bp[jp]);
        }
        if (more) {
            int nb = buf ^ 1;
            As[nb][lc + 0][lr] = av.x; As[nb][lc + 1][lr] = av.y;
            As[nb][lc + 2][lr] = av.z; As[nb][lc + 3][lr] = av.w;
            Bs[nb][lc + 0][lr] = wv.x; Bs[nb][lc + 1][lr] = wv.y;
            Bs[nb][lc + 2][lr] = wv.z; Bs[nb][lc + 3][lr] = wv.w;
        }
        __syncthreads();
        buf ^= 1;
    }

#pragma unroll
    for (int i = 0; i < 8; i++) {
        int m = m0 + tr*8 + i;
        float rs = (EP == 2) ? extra[m] : 0.f;
#pragma unroll
        for (int jp = 0; jp < 4; jp++) {
            float2 p = upk2(acc[i][jp]);
            float vals[2] = { p.x, p.y };
#pragma unroll
            for (int h = 0; h < 2; h++) {
                int n = n0 + tc*8 + jp*2 + h;
                float v = vals[h] + bias[n];
                if (EP == 1) v = 0.5f * v * (1.f + erff(v * 0.70710678118654752f));
                if (EP == 2) v *= rs;
                if (EP == 3) v += extra[(size_t)m * N + n];
                Cc[(size_t)m * N + n] = v;
            }
        }
    }
}

// ---------------- GRU persistent kernel -------------------------------------
#define NCTA_GRU 128
#define CHB 6   /* channels per CTA: 128*6 = 768 */
__global__ __launch_bounds__(192, 1)
void gru_kernel(const float* __restrict__ xi, const float* __restrict__ Whh,
                const float* __restrict__ bhh) {
    __shared__ float hs[Bn][Cn];
    __shared__ float gbuf[CHB][3][Bn];
    int tid = threadIdx.x, w = tid >> 5, lane = tid & 31;
    int c0 = blockIdx.x * CHB;
    int ch = c0 + w;  // warp's channel (6 warps)

    // recurrent weights resident in registers, packed as f32x2 pairs
    ull wp[3][6][2];
#pragma unroll
    for (int g = 0; g < 3; g++)
#pragma unroll
        for (int j = 0; j < 6; j++) {
            float4 v = __ldg((const float4*)(Whh + (size_t)(g*Cn + ch) * Cn) + (j*32 + lane));
            wp[g][j][0] = pk2(v.x, v.y);
            wp[g][j][1] = pk2(v.z, v.w);
        }

    bool is_comb = tid < (Bn * CHB);
    int bcomb = 0, ccomb = 0;
    float bhr = 0.f, bhz = 0.f, bhn = 0.f;
    if (is_comb) {
        bcomb = tid / CHB; ccomb = c0 + tid % CHB;
        bhr = __ldg(bhh + ccomb);
        bhz = __ldg(bhh + Cn + ccomb);
        bhn = __ldg(bhh + 2*Cn + ccomb);
    }

    unsigned target = NCTA_GRU;
    for (int t = 0; t < Tn; t++) {
        // stage h state (L1-bypass: other CTAs wrote it last step)
        const float4* hp = (const float4*)g_hstate;
        float4* hd = (float4*)&hs[0][0];
#pragma unroll
        for (int i = 0; i < 8; i++) hd[tid + i*192] = __ldcg(hp + tid + i*192);

        float xr = 0.f, xz = 0.f, xn = 0.f;
        if (is_comb) {
            const float* xrow = xi + ((size_t)bcomb*Tn + t) * G3C + ccomb;
            xr = __ldg(xrow); xz = __ldg(xrow + Cn); xn = __ldg(xrow + 2*Cn);
        }
        __syncthreads();

        ull acc2[3][Bn];
#pragma unroll
        for (int g = 0; g < 3; g++)
#pragma unroll
            for (int b = 0; b < Bn; b++) acc2[g][b] = 0ull;

#pragma unroll
        for (int j = 0; j < 6; j++) {
            ull h01[Bn], h23[Bn];
#pragma unroll
            for (int b = 0; b < Bn; b++) {
                float4 h4 = ((const float4*)&hs[b][0])[j*32 + lane];
                h01[b] = pk2(h4.x, h4.y);
                h23[b] = pk2(h4.z, h4.w);
            }
#pragma unroll
            for (int b = 0; b < Bn; b++) {
#pragma unroll
                for (int g = 0; g < 3; g++) {
                    fma2(acc2[g][b], wp[g][j][0], h01[b]);
                    fma2(acc2[g][b], wp[g][j][1], h23[b]);
                }
            }
        }
        // pair-collapse then lane reduce
        float acc[3][Bn];
#pragma unroll
        for (int g = 0; g < 3; g++)
#pragma unroll
            for (int b = 0; b < Bn; b++) {
                float2 p = upk2(acc2[g][b]);
                float v = p.x + p.y;
#pragma unroll
                for (int off = 16; off > 0; off >>= 1)
                    v += __shfl_xor_sync(0xffffffffu, v, off);
                acc[g][b] = v;
            }
        if (lane == 0) {
#pragma unroll
            for (int g = 0; g < 3; g++)
#pragma unroll
                for (int b = 0; b < Bn; b++) gbuf[w][g][b] = acc[g][b];
        }
        __syncthreads();

        if (is_comb) {
            int cc = tid % CHB;
            float hr = gbuf[cc][0][bcomb] + bhr;
            float hz = gbuf[cc][1][bcomb] + bhz;
            float hn = gbuf[cc][2][bcomb] + bhn;
            float r = 1.f / (1.f + expf(-(xr + hr)));
            float z = 1.f / (1.f + expf(-(xz + hz)));
            float n = tanhf(xn + r * hn);
            float hold = hs[bcomb][ccomb];
            float hnew = (1.f - z) * n + z * hold;
            g_hstate[bcomb*Cn + ccomb] = hnew;
            g_hrnn[((size_t)bcomb*Tn + t) * Cn + ccomb] = hnew;
            __threadfence();
        }
        __syncthreads();
        if (tid == 0) {
            atomicAdd(&g_bar, 1u);
            volatile unsigned* p = &g_bar;
            while (*p < target) __nanosleep(64);
        }
        target += NCTA_GRU;
        __syncthreads();
    }
}

// ---------------- gate MLP / energy -----------------------------------------
__global__ __launch_bounds__(128)
void energy_kernel(const float* __restrict__ gw1, const float* __restrict__ gb1,
                   const float* __restrict__ gw2, const float* __restrict__ gb2,
                   float* __restrict__ out_energy) {
    int tok = blockIdx.x;
    int tid = threadIdx.x, w = tid >> 5, lane = tid & 31;
    __shared__ float dots[32];
    const float* h = g_hrnn + (size_t)tok * Cn;
#pragma unroll
    for (int jj = 0; jj < 8; jj++) {
        int j = w * 8 + jj;
        const float* wr = gw1 + (size_t)j * Cn;
        float p = 0.f;
        for (int k = lane; k < Cn; k += 32) p += h[k] * wr[k];
#pragma unroll
        for (int off = 16; off > 0; off >>= 1) p += __shfl_xor_sync(0xffffffffu, p, off);
        if (lane == 0) dots[j] = p;
    }
    __syncthreads();
    if (tid == 0) {
        float a = gb2[0];
#pragma unroll
        for (int j = 0; j < 32; j++) a += tanhf(dots[j] + gb1[j]) * gw2[j];
        float e = 1.f / (1.f + expf(-a));
        g_energy[tok] = e;
        out_energy[tok] = e;
        if (e > 0.5f) atomicAdd(&g_active, 1);
    }
}

// ---------------- exact top-k via bitonic sort -------------------------------
__global__ __launch_bounds__(1024)
void topk_kernel() {
    __shared__ unsigned long long keys[Tn];
    __shared__ int sel[KSEL];
    int b = blockIdx.x, tid = threadIdx.x;
    for (int e = tid; e < Tn; e += 1024) {
        unsigned u = __float_as_uint(g_energy[b*Tn + e]);
        u = (u & 0x80000000u) ? ~u : (u | 0x80000000u);
        keys[e] = ((unsigned long long)u << 32) | (unsigned)(Tn - 1 - e);
    }
    __syncthreads();
    // descending sort (ties -> lower index first)
    for (int k = 2; k <= Tn; k <<= 1)
        for (int j = k >> 1; j > 0; j >>= 1) {
            int p = tid;
            int e = ((p & ~(j - 1)) << 1) | (p & (j - 1));
            int f = e | j;
            unsigned long long a = keys[e], c = keys[f];
            bool up = ((e & k) == 0);
            bool sw = up ? (a < c) : (a > c);
            if (sw) { keys[e] = c; keys[f] = a; }
            __syncthreads();
        }
    if (tid < KSEL) sel[tid] = Tn - 1 - (int)(keys[tid] & 0xffffffffull);
    __syncthreads();
    // ascending sort of selected indices
    for (int k = 2; k <= KSEL; k <<= 1)
        for (int j = k >> 1; j > 0; j >>= 1) {
            if (tid < KSEL/2) {
                int p = tid;
                int e = ((p & ~(j - 1)) << 1) | (p & (j - 1));
                int f = e | j;
                int a = sel[e], c = sel[f];
                bool up = ((e & k) == 0);
                bool sw = up ? (a > c) : (a < c);
                if (sw) { sel[e] = c; sel[f] = a; }
            }
            __syncthreads();
        }
    if (tid < KSEL) g_idx[b*KSEL + tid] = sel[tid];
}

// ---------------- gather selected tokens -------------------------------------
__global__ __launch_bounds__(192)
void gather_kernel() {
    int bk = blockIdx.x;
    int b = bk / KSEL;
    int t = g_idx[bk];
    if (threadIdx.x == 0) {
        g_gsel[bk] = g_energy[b*Tn + t];
        g_selmap[b*Tn + t] = bk % KSEL;
    }
    const float4* src = (const float4*)(g_hrnn + ((size_t)b*Tn + t) * Cn);
    float4* dst = (float4*)(g_xsel + (size_t)bk * Cn);
    dst[threadIdx.x] = src[threadIdx.x];
}

// ---------------- flash attention (causal, hd=64, Klen=1024) -----------------
__global__ __launch_bounds__(256)
void attn_kernel() {
    extern __shared__ float sm[];
    float* Qs = sm;                 // 64 x 65
    float* Ks = Qs + 64*65;         // 64 x 65
    float* Ps = Ks + 64*65;         // 64 x 65
    float* Vs = Ps + 64*65;         // 64 x 64
    int qt = blockIdx.x, bh = blockIdx.y;
    int b = bh / Hn, h = bh % Hn;
    int tid = threadIdx.x, tr = tid >> 4, tc = tid & 15;
    int q0 = qt * 64;
    const float* base = g_qkv + (size_t)b * KSEL * G3C;

    for (int i = tid; i < 1024; i += 256) {
        int r = i >> 4, d4 = i & 15;
        float4 v = __ldg((const float4*)(base + (size_t)(q0 + r)*G3C + h*64) + d4);
        Qs[r*65 + d4*4 + 0] = v.x; Qs[r*65 + d4*4 + 1] = v.y;
        Qs[r*65 + d4*4 + 2] = v.z; Qs[r*65 + d4*4 + 3] = v.w;
    }

    ull op[4][2];
    float m[4], l[4];
#pragma unroll
    for (int i = 0; i < 4; i++) {
        m[i] = -1e30f; l[i] = 0.f;
        op[i][0] = 0ull; op[i][1] = 0ull;
    }

    for (int kt = 0; kt <= qt; kt++) {
        int k0 = kt * 64;
        for (int i = tid; i < 1024; i += 256) {
            int c = i >> 4, d4 = i & 15;
            float4 kv = __ldg((const float4*)(base + (size_t)(k0 + c)*G3C + Cn + h*64) + d4);
            Ks[c*65 + d4*4 + 0] = kv.x; Ks[c*65 + d4*4 + 1] = kv.y;
            Ks[c*65 + d4*4 + 2] = kv.z; Ks[c*65 + d4*4 + 3] = kv.w;
            float4 vv = __ldg((const float4*)(base + (size_t)(k0 + c)*G3C + 2*Cn + h*64) + d4);
            ((float4*)(Vs + c*64))[d4] = vv;
        }
        __syncthreads();

        ull sp[4][2];
#pragma unroll
        for (int i = 0; i < 4; i++) { sp[i][0] = 0ull; sp[i][1] = 0ull; }
        for (int kk = 0; kk < 64; kk++) {
            ull ad[4], bp[2];
#pragma unroll
            for (int i = 0; i < 4; i++) ad[i] = dup2(Qs[(tr*4 + i)*65 + kk]);
            {
                float bb0 = Ks[(tc*4 + 0)*65 + kk];
                float bb1 = Ks[(tc*4 + 1)*65 + kk];
                float bb2 = Ks[(tc*4 + 2)*65 + kk];
                float bb3 = Ks[(tc*4 + 3)*65 + kk];
                bp[0] = pk2(bb0, bb1); bp[1] = pk2(bb2, bb3);
            }
#pragma unroll
            for (int i = 0; i < 4; i++) {
                fma2(sp[i][0], ad[i], bp[0]);
                fma2(sp[i][1], ad[i], bp[1]);
            }
        }
        float s[4][4];
#pragma unroll
        for (int i = 0; i < 4; i++) {
            float2 p0 = upk2(sp[i][0]), p1 = upk2(sp[i][1]);
            s[i][0] = p0.x * 0.125f; s[i][1] = p0.y * 0.125f;
            s[i][2] = p1.x * 0.125f; s[i][3] = p1.y * 0.125f;
        }
        if (kt == qt) {
#pragma unroll
            for (int i = 0; i < 4; i++)
#pragma unroll
                for (int j = 0; j < 4; j++)
                    if (k0 + tc*4 + j > q0 + tr*4 + i) s[i][j] = -1e30f;
        }
        // online softmax
#pragma unroll
        for (int i = 0; i < 4; i++) {
            float rm = s[i][0];
#pragma unroll
            for (int j = 1; j < 4; j++) rm = fmaxf(rm, s[i][j]);
#pragma unroll
            for (int off = 8; off > 0; off >>= 1)
                rm = fmaxf(rm, __shfl_xor_sync(0xffffffffu, rm, off));
            float mn = fmaxf(m[i], rm);
            float alpha = expf(m[i] - mn);
            float rs = 0.f;
#pragma unroll
            for (int j = 0; j < 4; j++) {
                s[i][j] = expf(s[i][j] - mn);
                rs += s[i][j];
            }
#pragma unroll
            for (int off = 8; off > 0; off >>= 1)
                rs += __shfl_xor_sync(0xffffffffu, rs, off);
            l[i] = l[i] * alpha + rs;
            m[i] = mn;
            ull da = dup2(alpha);
            op[i][0] = mul2(op[i][0], da);
            op[i][1] = mul2(op[i][1], da);
#pragma unroll
            for (int j = 0; j < 4; j++) Ps[(tr*4 + i)*65 + tc*4 + j] = s[i][j];
        }
        __syncthreads();
        for (int c = 0; c < 64; c++) {
            ull pd[4], vp[2];
#pragma unroll
            for (int i = 0; i < 4; i++) pd[i] = dup2(Ps[(tr*4 + i)*65 + c]);
            {
                float4 vv = *(const float4*)(Vs + c*64 + tc*4);
                vp[0] = pk2(vv.x, vv.y); vp[1] = pk2(vv.z, vv.w);
            }
#pragma unroll
            for (int i = 0; i < 4; i++) {
                fma2(op[i][0], pd[i], vp[0]);
                fma2(op[i][1], pd[i], vp[1]);
            }
        }
        __syncthreads();
    }
#pragma unroll
    for (int i = 0; i < 4; i++) {
        float inv = 1.f / l[i];
        int row = b * KSEL + q0 + tr*4 + i;
        float2 p0 = upk2(op[i][0]), p1 = upk2(op[i][1]);
        float* dst = g_y + (size_t)row * Cn + h*64 + tc*4;
        dst[0] = p0.x * inv; dst[1] = p0.y * inv;
        dst[2] = p1.x * inv; dst[3] = p1.y * inv;
    }
}

// ---------------- LayerNorm with fused scatter-add ---------------------------
__global__ __launch_bounds__(256)
void ln_kernel(const float* __restrict__ g, const float* __restrict__ bb) {
    __shared__ float xrow[Cn];
    __shared__ float rbuf[16];
    int tok = blockIdx.x, tid = threadIdx.x;
    int b = tok >> 11;
    int sel = g_selmap[tok];
    float s = 0.f, s2 = 0.f;
    for (int c = tid; c < Cn; c += 256) {
        float v = g_hrnn[(size_t)tok*Cn + c];
        if (sel >= 0) v += g_weighted[((size_t)(b*KSEL + sel))*Cn + c];
        xrow[c] = v; s += v; s2 += v*v;
    }
#pragma unroll
    for (int off = 16; off > 0; off >>= 1) {
        s  += __shfl_xor_sync(0xffffffffu, s, off);
        s2 += __shfl_xor_sync(0xffffffffu, s2, off);
    }
    int w = tid >> 5;
    if ((tid & 31) == 0) { rbuf[w] = s; rbuf[8 + w] = s2; }
    __syncthreads();
    if (tid == 0) {
        float S = 0.f, S2 = 0.f;
        for (int i = 0; i < 8; i++) { S += rbuf[i]; S2 += rbuf[8 + i]; }
        float mu = S / (float)Cn;
        float var = S2 / (float)Cn - mu*mu;
        rbuf[0] = mu; rbuf[1] = rsqrtf(var + 1e-5f);
    }
    __syncthreads();
    float mu = rbuf[0], inv = rbuf[1];
    for (int c = tid; c < Cn; c += 256)
        g_hln[(size_t)tok*Cn + c] = (xrow[c] - mu) * inv * g[c] + bb[c];
}

// ---------------- finalize ----------------------------------------------------
__global__ void finalize_kernel(float* out) {
    out[(size_t)BT*Cn + BT] = (float)g_active;
}

// ---------------- launcher ----------------------------------------------------
extern "C" void kernel_launch(void* const* d_in, const int* in_sizes, int n_in,
                              void* d_out, int out_size) {
    const float* x      = (const float*)d_in[0];
    const float* W_ih   = (const float*)d_in[1];
    const float* W_hh   = (const float*)d_in[2];
    const float* b_ih   = (const float*)d_in[3];
    const float* b_hh   = (const float*)d_in[4];
    const float* gate_w1= (const float*)d_in[5];
    const float* gate_b1= (const float*)d_in[6];
    const float* gate_w2= (const float*)d_in[7];
    const float* gate_b2= (const float*)d_in[8];
    const float* qkv_w  = (const float*)d_in[9];
    const float* qkv_b  = (const float*)d_in[10];
    const float* proj_w = (const float*)d_in[11];
    const float* proj_b = (const float*)d_in[12];
    const float* ln_g   = (const float*)d_in[13];
    const float* ln_b   = (const float*)d_in[14];
    const float* ffn_w1 = (const float*)d_in[15];
    const float* ffn_b1 = (const float*)d_in[16];
    const float* ffn_w2 = (const float*)d_in[17];
    const float* ffn_b2 = (const float*)d_in[18];
    float* out = (float*)d_out;

    // device-global scratch addresses
    float *p_xi, *p_xsel, *p_qkv, *p_y, *p_weighted, *p_hln, *p_mid, *p_energy_out;
    cudaGetSymbolAddress((void**)&p_xi,       g_xi);
    cudaGetSymbolAddress((void**)&p_xsel,     g_xsel);
    cudaGetSymbolAddress((void**)&p_qkv,      g_qkv);
    cudaGetSymbolAddress((void**)&p_y,        g_y);
    cudaGetSymbolAddress((void**)&p_weighted, g_weighted);
    cudaGetSymbolAddress((void**)&p_hln,      g_hln);
    cudaGetSymbolAddress((void**)&p_mid,      g_mid);
    float* p_gsel; cudaGetSymbolAddress((void**)&p_gsel, g_gsel);
    p_energy_out = out + (size_t)BT*Cn;

    const int ATTN_SMEM = (3*64*65 + 64*64) * 4;
    cudaFuncSetAttribute(attn_kernel, cudaFuncAttributeMaxDynamicSharedMemorySize, ATTN_SMEM);

    // 0) init scratch state
    init_kernel<<<64, 256>>>();

    // 1) xi = x @ W_ih^T + b_ih   [16384, 2304]
    gemm_kernel<0><<<dim3(G3C/128, BT/128), 256>>>(x, W_ih, b_ih, nullptr, p_xi, BT, G3C, Cn);

    // 2) GRU scan (persistent, global barrier per step)
    gru_kernel<<<NCTA_GRU, 192>>>(p_xi, W_hh, b_hh);

    // 3) gate MLP energy (+ writes energy output + active count)
    energy_kernel<<<BT, 128>>>(gate_w1, gate_b1, gate_w2, gate_b2, p_energy_out);

    // 4) exact top-k + ascending index sort
    topk_kernel<<<Bn, 1024>>>();

    // 5) gather selected tokens; build inverse map + gate values
    gather_kernel<<<BKn, 192>>>();

    // 6) qkv = x_sel @ qkv_w^T + qkv_b  [8192, 2304]
    gemm_kernel<0><<<dim3(G3C/128, BKn/128), 256>>>(p_xsel, qkv_w, qkv_b, nullptr, p_qkv, BKn, G3C, Cn);

    // 7) causal flash attention
    attn_kernel<<<dim3(KSEL/64, Bn*Hn), 256, ATTN_SMEM>>>();

    // 8) weighted = (y @ proj_w^T + proj_b) * g_sel  [8192, 768]
    gemm_kernel<2><<<dim3(Cn/128, BKn/128), 256>>>(p_y, proj_w, proj_b, p_gsel, p_weighted, BKn, Cn, Cn);

    // 9) LayerNorm(h_rnn + scatter(weighted))
    ln_kernel<<<BT, 256>>>(ln_g, ln_b);

    // 10) mid = gelu(h_ln @ ffn_w1^T + ffn_b1)  [16384, 3072]
    gemm_kernel<1><<<dim3(DFF/128, BT/128), 256>>>(p_hln, ffn_w1, ffn_b1, nullptr, p_mid, BT, DFF, Cn);

    // 11) out_h = h_ln + mid @ ffn_w2^T + ffn_b2  -> d_out[0 : BT*C]
    gemm_kernel<3><<<dim3(Cn/128, BT/128), 256>>>(p_mid, ffn_w2, ffn_b2, p_hln, out, BT, Cn, DFF);

    // 12) active count
    finalize_kernel<<<1, 1>>>(out);

    (void)in_sizes; (void)n_in; (void)out_size;
}

// round 3
// speedup vs baseline: 1.2933x; 1.2439x over previous
#include <cuda_runtime.h>
#include <math.h>
#include <stdint.h>

#define Bn 8
#define Tn 2048
#define Cn 768
#define Hn 12
#define KSEL 1024
#define DFF 3072
#define BT (Bn*Tn)      /* 16384 */
#define BKn (Bn*KSEL)   /* 8192 */
#define G3C (3*Cn)      /* 2304 */

typedef unsigned long long ull;

// ---------------- f32x2 packed helpers (FFMA2 path, sm_100+) ----------------
__device__ __forceinline__ ull pk2(float x, float y) {
    ull r; asm("mov.b64 %0, {%1, %2};" : "=l"(r) : "f"(x), "f"(y)); return r;
}
__device__ __forceinline__ ull dup2(float x) { return pk2(x, x); }
__device__ __forceinline__ void fma2(ull &acc, ull a, ull b) {
    asm("fma.rn.f32x2 %0, %1, %2, %0;" : "+l"(acc) : "l"(a), "l"(b));
}
__device__ __forceinline__ ull mul2(ull a, ull b) {
    ull r; asm("mul.rn.f32x2 %0, %1, %2;" : "=l"(r) : "l"(a), "l"(b)); return r;
}
__device__ __forceinline__ float2 upk2(ull v) {
    float2 r; asm("mov.b64 {%0, %1}, %2;" : "=f"(r.x), "=f"(r.y) : "l"(v)); return r;
}
__device__ __forceinline__ unsigned cvt_tf32(float x) {
    unsigned u; asm("cvt.rna.tf32.f32 %0, %1;" : "=r"(u) : "f"(x)); return u;
}

// ---------------- scratch (device globals; no allocation allowed) ----------
__device__ float g_xi[(size_t)BT*G3C];
__device__ float g_hrnn[(size_t)BT*Cn];
__device__ float g_hstate[Bn*Cn];
__device__ float g_energy[BT];
__device__ int   g_idx[BKn];
__device__ int   g_selmap[BT];
__device__ float g_xsel[(size_t)BKn*Cn];
__device__ float g_gsel[BKn];
__device__ float g_qkv[(size_t)BKn*G3C];
__device__ float g_y[(size_t)BKn*Cn];
__device__ float g_weighted[(size_t)BKn*Cn];
__device__ float g_hln[(size_t)BT*Cn];
__device__ float g_mid[(size_t)BT*DFF];
__device__ unsigned g_bar;
__device__ int g_active;

// ---------------- init ------------------------------------------------------
__global__ void init_kernel() {
    int tid = blockIdx.x * blockDim.x + threadIdx.x;
    if (tid == 0) { g_bar = 0u; g_active = 0; }
    for (int i = tid; i < Bn*Cn; i += gridDim.x*blockDim.x) g_hstate[i] = 0.f;
    for (int i = tid; i < BT;    i += gridDim.x*blockDim.x) g_selmap[i] = -1;
}

// ============================================================================
// TF32 tensor-core GEMM: C[M,N] = A[M,K] @ W[N,K]^T + bias
// mma.sync.m16n8k8.tf32; 128x128 CTA tile, 16-wide K tiles, double buffered.
// Fragment-permuted SMEM layout: one LDS.128 = full A fragment, LDS.64 = B frag.
// EP: 0 none, 1 gelu(exact erf), 2 row-scale(extra[m]), 3 residual(extra[m*N+n])
// ============================================================================
template<int EP>
__global__ __launch_bounds__(256)
void gemm_tc_kernel(const float* __restrict__ A, const float* __restrict__ W,
                    const float* __restrict__ bias, const float* __restrict__ extra,
                    float* __restrict__ Cc, int M, int N, int K) {
    // per-buffer: A 2048 floats (8KB), W 2048 floats (8KB); double buffered.
    __shared__ float Asm[2][2048];
    __shared__ float Wsm[2][2048];

    int tid = threadIdx.x;
    int m0 = blockIdx.y * 128, n0 = blockIdx.x * 128;
    int wid = tid >> 5, L = tid & 31;
    int warp_m = wid >> 2;        // 0..1 (64 rows each)
    int warp_n = wid & 3;         // 0..3 (32 cols each)
    int r = L >> 2, c4 = L & 3;
    int slot = 4*r + (c4 ^ (r & 3));   // swizzled lane slot for frag reads

    float cacc[4][4][4];
#pragma unroll
    for (int mt = 0; mt < 4; mt++)
#pragma unroll
        for (int nt = 0; nt < 4; nt++)
#pragma unroll
            for (int q = 0; q < 4; q++) cacc[mt][nt][q] = 0.f;

    // global-load assignment: idx -> (row, k-quad)
    int idxA0 = tid, idxA1 = tid + 256;

    // ---- prologue: tile 0 into buffer 0 ----
    {
#pragma unroll
        for (int it = 0; it < 2; it++) {
            int idx = (it == 0) ? idxA0 : idxA1;
            int m = idx >> 2, kq = idx & 3;
            float4 v = *(const float4*)(A + (size_t)(m0 + m) * K + kq*4);
            int sb = (((m>>4)*2 + (kq>>1))*32 + 4*(m&7));
            int comp = (kq&1)*2 + ((m>>3)&1);
            float vl[4] = {v.x, v.y, v.z, v.w};
#pragma unroll
            for (int e = 0; e < 4; e++)
                Asm[0][(sb + (e ^ (m&3)))*4 + comp] = __uint_as_float(cvt_tf32(vl[e]));

            int n = idx >> 2;
            float4 wv = *(const float4*)(W + (size_t)(n0 + n) * K + kq*4);
            int sbw = (((n>>3)*2 + (kq>>1))*32 + 4*(n&7));
            float wl[4] = {wv.x, wv.y, wv.z, wv.w};
#pragma unroll
            for (int e = 0; e < 4; e++)
                Wsm[0][(sbw + (e ^ (n&3)))*2 + (kq&1)] = __uint_as_float(cvt_tf32(wl[e]));
        }
    }
    __syncthreads();

    int buf = 0;
    for (int kt = 16; kt <= K; kt += 16) {
        bool more = (kt < K);
        float4 pvA[2], pvW[2];
        if (more) {
#pragma unroll
            for (int it = 0; it < 2; it++) {
                int idx = (it == 0) ? idxA0 : idxA1;
                int m = idx >> 2, kq = idx & 3;
                pvA[it] = *(const float4*)(A + (size_t)(m0 + m) * K + kt + kq*4);
                pvW[it] = *(const float4*)(W + (size_t)(n0 + m) * K + kt + kq*4);
            }
        }

        // ---- compute current buffer ----
#pragma unroll
        for (int s = 0; s < 2; s++) {
            float4 af[4]; float2 bf[4];
#pragma unroll
            for (int mt = 0; mt < 4; mt++)
                af[mt] = *(const float4*)&Asm[buf][((((warp_m*4 + mt)*2 + s)*32) + slot)*4];
#pragma unroll
            for (int nt = 0; nt < 4; nt++)
                bf[nt] = *(const float2*)&Wsm[buf][((((warp_n*4 + nt)*2 + s)*32) + slot)*2];
#pragma unroll
            for (int mt = 0; mt < 4; mt++) {
                unsigned a0 = __float_as_uint(af[mt].x), a1 = __float_as_uint(af[mt].y);
                unsigned a2 = __float_as_uint(af[mt].z), a3 = __float_as_uint(af[mt].w);
#pragma unroll
                for (int nt = 0; nt < 4; nt++) {
                    unsigned b0 = __float_as_uint(bf[nt].x), b1 = __float_as_uint(bf[nt].y);
                    asm volatile(
                        "mma.sync.aligned.m16n8k8.row.col.f32.tf32.tf32.f32 "
                        "{%0,%1,%2,%3}, {%4,%5,%6,%7}, {%8,%9}, {%0,%1,%2,%3};"
                        : "+f"(cacc[mt][nt][0]), "+f"(cacc[mt][nt][1]),
                          "+f"(cacc[mt][nt][2]), "+f"(cacc[mt][nt][3])
                        : "r"(a0), "r"(a1), "r"(a2), "r"(a3), "r"(b0), "r"(b1));
                }
            }
        }

        if (more) {
            int nb = buf ^ 1;
#pragma unroll
            for (int it = 0; it < 2; it++) {
                int idx = (it == 0) ? idxA0 : idxA1;
                int m = idx >> 2, kq = idx & 3;
                int sb = (((m>>4)*2 + (kq>>1))*32 + 4*(m&7));
                int comp = (kq&1)*2 + ((m>>3)&1);
                float vl[4] = {pvA[it].x, pvA[it].y, pvA[it].z, pvA[it].w};
#pragma unroll
                for (int e = 0; e < 4; e++)
                    Asm[nb][(sb + (e ^ (m&3)))*4 + comp] = __uint_as_float(cvt_tf32(vl[e]));
                int sbw = (((m>>3)*2 + (kq>>1))*32 + 4*(m&7));
                float wl[4] = {pvW[it].x, pvW[it].y, pvW[it].z, pvW[it].w};
#pragma unroll
                for (int e = 0; e < 4; e++)
                    Wsm[nb][(sbw + (e ^ (m&3)))*2 + (kq&1)] = __uint_as_float(cvt_tf32(wl[e]));
            }
        }
        __syncthreads();
        buf ^= 1;
    }

    // ---- epilogue ----
#pragma unroll
    for (int mt = 0; mt < 4; mt++) {
        int gm = m0 + warp_m*64 + mt*16 + r;
        float rs0 = (EP == 2) ? extra[gm] : 0.f;
        float rs1 = (EP == 2) ? extra[gm + 8] : 0.f;
#pragma unroll
        for (int nt = 0; nt < 4; nt++) {
            int gn = n0 + warp_n*32 + nt*8 + 2*c4;
            float b0 = bias[gn], b1 = bias[gn + 1];
#pragma unroll
            for (int half = 0; half < 2; half++) {
                int row = gm + half*8;
                float v0 = cacc[mt][nt][half*2 + 0] + b0;
                float v1 = cacc[mt][nt][half*2 + 1] + b1;
                if (EP == 1) {
                    v0 = 0.5f * v0 * (1.f + erff(v0 * 0.70710678118654752f));
                    v1 = 0.5f * v1 * (1.f + erff(v1 * 0.70710678118654752f));
                }
                if (EP == 2) { float rs = half ? rs1 : rs0; v0 *= rs; v1 *= rs; }
                if (EP == 3) {
                    v0 += extra[(size_t)row * N + gn];
                    v1 += extra[(size_t)row * N + gn + 1];
                }
                float2 o = make_float2(v0, v1);
                *(float2*)(Cc + (size_t)row * N + gn) = o;
            }
        }
    }
}

// ---------------- fp32 SGEMM (FFMA2) — used ONLY for xi (pre-selection) ------
__global__ __launch_bounds__(256, 2)
void gemm_kernel(const float* __restrict__ A, const float* __restrict__ W,
                 const float* __restrict__ bias, const float* __restrict__ extra,
                 float* __restrict__ Cc, int M, int N, int K) {
    __shared__ float As[2][8][128];
    __shared__ float Bs[2][8][128];
    int tid = threadIdx.x;
    int m0 = blockIdx.y * 128, n0 = blockIdx.x * 128;
    int tr = tid >> 4, tc = tid & 15;

    ull acc[8][4];
#pragma unroll
    for (int i = 0; i < 8; i++)
#pragma unroll
        for (int j = 0; j < 4; j++) acc[i][j] = 0ull;

    int lr = tid >> 1;
    int lc = (tid & 1) * 4;
    const float* Ap = A + (size_t)(m0 + lr) * K + lc;
    const float* Wp = W + (size_t)(n0 + lr) * K + lc;

    {
        float4 av = *(const float4*)(Ap);
        float4 wv = *(const float4*)(Wp);
        As[0][lc + 0][lr] = av.x; As[0][lc + 1][lr] = av.y;
        As[0][lc + 2][lr] = av.z; As[0][lc + 3][lr] = av.w;
        Bs[0][lc + 0][lr] = wv.x; Bs[0][lc + 1][lr] = wv.y;
        Bs[0][lc + 2][lr] = wv.z; Bs[0][lc + 3][lr] = wv.w;
    }
    __syncthreads();

    int buf = 0;
    for (int kt = 8; kt <= K; kt += 8) {
        float4 av, wv;
        bool more = (kt < K);
        if (more) {
            av = *(const float4*)(Ap + kt);
            wv = *(const float4*)(Wp + kt);
        }
#pragma unroll
        for (int kk = 0; kk < 8; kk++) {
            float4 a0 = *(const float4*)&As[buf][kk][tr*8];
            float4 a1 = *(const float4*)&As[buf][kk][tr*8 + 4];
            float4 b0 = *(const float4*)&Bs[buf][kk][tc*8];
            float4 b1 = *(const float4*)&Bs[buf][kk][tc*8 + 4];
            ull bp[4] = { pk2(b0.x,b0.y), pk2(b0.z,b0.w),
                          pk2(b1.x,b1.y), pk2(b1.z,b1.w) };
            ull ad[8] = { dup2(a0.x), dup2(a0.y), dup2(a0.z), dup2(a0.w),
                          dup2(a1.x), dup2(a1.y), dup2(a1.z), dup2(a1.w) };
#pragma unroll
            for (int i = 0; i < 8; i++)
#pragma unroll
                for (int jp = 0; jp < 4; jp++) fma2(acc[i][jp], ad[i], bp[jp]);
        }
        if (more) {
            int nb = buf ^ 1;
            As[nb][lc + 0][lr] = av.x; As[nb][lc + 1][lr] = av.y;
            As[nb][lc + 2][lr] = av.z; As[nb][lc + 3][lr] = av.w;
            Bs[nb][lc + 0][lr] = wv.x; Bs[nb][lc + 1][lr] = wv.y;
            Bs[nb][lc + 2][lr] = wv.z; Bs[nb][lc + 3][lr] = wv.w;
        }
        __syncthreads();
        buf ^= 1;
    }

#pragma unroll
    for (int i = 0; i < 8; i++) {
        int m = m0 + tr*8 + i;
#pragma unroll
        for (int jp = 0; jp < 4; jp++) {
            float2 p = upk2(acc[i][jp]);
            float vals[2] = { p.x, p.y };
#pragma unroll
            for (int h = 0; h < 2; h++) {
                int n = n0 + tc*8 + jp*2 + h;
                float v = vals[h] + bias[n];
                Cc[(size_t)m * N + n] = v;
            }
        }
    }
    (void)extra;
}

// ---------------- GRU persistent kernel -------------------------------------
#define NCTA_GRU 128
#define CHB 6   /* channels per CTA: 128*6 = 768 */
__global__ __launch_bounds__(192, 1)
void gru_kernel(const float* __restrict__ xi, const float* __restrict__ Whh,
                const float* __restrict__ bhh) {
    __shared__ float hs[Bn][Cn];
    __shared__ float gbuf[CHB][3][Bn];
    int tid = threadIdx.x, w = tid >> 5, lane = tid & 31;
    int c0 = blockIdx.x * CHB;
    int ch = c0 + w;

    ull wp[3][6][2];
#pragma unroll
    for (int g = 0; g < 3; g++)
#pragma unroll
        for (int j = 0; j < 6; j++) {
            float4 v = __ldg((const float4*)(Whh + (size_t)(g*Cn + ch) * Cn) + (j*32 + lane));
            wp[g][j][0] = pk2(v.x, v.y);
            wp[g][j][1] = pk2(v.z, v.w);
        }

    bool is_comb = tid < (Bn * CHB);
    int bcomb = 0, ccomb = 0;
    float bhr = 0.f, bhz = 0.f, bhn = 0.f;
    if (is_comb) {
        bcomb = tid / CHB; ccomb = c0 + tid % CHB;
        bhr = __ldg(bhh + ccomb);
        bhz = __ldg(bhh + Cn + ccomb);
        bhn = __ldg(bhh + 2*Cn + ccomb);
    }

    unsigned target = NCTA_GRU;
    for (int t = 0; t < Tn; t++) {
        const float4* hp = (const float4*)g_hstate;
        float4* hd = (float4*)&hs[0][0];
#pragma unroll
        for (int i = 0; i < 8; i++) hd[tid + i*192] = __ldcg(hp + tid + i*192);

        float xr = 0.f, xz = 0.f, xn = 0.f;
        if (is_comb) {
            const float* xrow = xi + ((size_t)bcomb*Tn + t) * G3C + ccomb;
            xr = __ldg(xrow); xz = __ldg(xrow + Cn); xn = __ldg(xrow + 2*Cn);
        }
        __syncthreads();

        ull acc2[3][Bn];
#pragma unroll
        for (int g = 0; g < 3; g++)
#pragma unroll
            for (int b = 0; b < Bn; b++) acc2[g][b] = 0ull;

#pragma unroll
        for (int j = 0; j < 6; j++) {
            ull h01[Bn], h23[Bn];
#pragma unroll
            for (int b = 0; b < Bn; b++) {
                float4 h4 = ((const float4*)&hs[b][0])[j*32 + lane];
                h01[b] = pk2(h4.x, h4.y);
                h23[b] = pk2(h4.z, h4.w);
            }
#pragma unroll
            for (int b = 0; b < Bn; b++) {
#pragma unroll
                for (int g = 0; g < 3; g++) {
                    fma2(acc2[g][b], wp[g][j][0], h01[b]);
                    fma2(acc2[g][b], wp[g][j][1], h23[b]);
                }
            }
        }
        float acc[3][Bn];
#pragma unroll
        for (int g = 0; g < 3; g++)
#pragma unroll
            for (int b = 0; b < Bn; b++) {
                float2 p = upk2(acc2[g][b]);
                float v = p.x + p.y;
#pragma unroll
                for (int off = 16; off > 0; off >>= 1)
                    v += __shfl_xor_sync(0xffffffffu, v, off);
                acc[g][b] = v;
            }
        if (lane == 0) {
#pragma unroll
            for (int g = 0; g < 3; g++)
#pragma unroll
                for (int b = 0; b < Bn; b++) gbuf[w][g][b] = acc[g][b];
        }
        __syncthreads();

        if (is_comb) {
            int cc = tid % CHB;
            float hr = gbuf[cc][0][bcomb] + bhr;
            float hz = gbuf[cc][1][bcomb] + bhz;
            float hn = gbuf[cc][2][bcomb] + bhn;
            float r = 1.f / (1.f + expf(-(xr + hr)));
            float z = 1.f / (1.f + expf(-(xz + hz)));
            float n = tanhf(xn + r * hn);
            float hold = hs[bcomb][ccomb];
            float hnew = (1.f - z) * n + z * hold;
            g_hstate[bcomb*Cn + ccomb] = hnew;
            g_hrnn[((size_t)bcomb*Tn + t) * Cn + ccomb] = hnew;
            __threadfence();
        }
        __syncthreads();
        if (tid == 0) {
            atomicAdd(&g_bar, 1u);
            volatile unsigned* p = &g_bar;
            while (*p < target) __nanosleep(64);
        }
        target += NCTA_GRU;
        __syncthreads();
    }
}

// ---------------- gate MLP / energy -----------------------------------------
__global__ __launch_bounds__(128)
void energy_kernel(const float* __restrict__ gw1, const float* __restrict__ gb1,
                   const float* __restrict__ gw2, const float* __restrict__ gb2,
                   float* __restrict__ out_energy) {
    int tok = blockIdx.x;
    int tid = threadIdx.x, w = tid >> 5, lane = tid & 31;
    __shared__ float dots[32];
    const float* h = g_hrnn + (size_t)tok * Cn;
#pragma unroll
    for (int jj = 0; jj < 8; jj++) {
        int j = w * 8 + jj;
        const float* wr = gw1 + (size_t)j * Cn;
        float p = 0.f;
        for (int k = lane; k < Cn; k += 32) p += h[k] * wr[k];
#pragma unroll
        for (int off = 16; off > 0; off >>= 1) p += __shfl_xor_sync(0xffffffffu, p, off);
        if (lane == 0) dots[j] = p;
    }
    __syncthreads();
    if (tid == 0) {
        float a = gb2[0];
#pragma unroll
        for (int j = 0; j < 32; j++) a += tanhf(dots[j] + gb1[j]) * gw2[j];
        float e = 1.f / (1.f + expf(-a));
        g_energy[tok] = e;
        out_energy[tok] = e;
        if (e > 0.5f) atomicAdd(&g_active, 1);
    }
}

// ---------------- exact top-k via bitonic sort -------------------------------
__global__ __launch_bounds__(1024)
void topk_kernel() {
    __shared__ unsigned long long keys[Tn];
    __shared__ int sel[KSEL];
    int b = blockIdx.x, tid = threadIdx.x;
    for (int e = tid; e < Tn; e += 1024) {
        unsigned u = __float_as_uint(g_energy[b*Tn + e]);
        u = (u & 0x80000000u) ? ~u : (u | 0x80000000u);
        keys[e] = ((unsigned long long)u << 32) | (unsigned)(Tn - 1 - e);
    }
    __syncthreads();
    for (int k = 2; k <= Tn; k <<= 1)
        for (int j = k >> 1; j > 0; j >>= 1) {
            int p = tid;
            int e = ((p & ~(j - 1)) << 1) | (p & (j - 1));
            int f = e | j;
            unsigned long long a = keys[e], c = keys[f];
            bool up = ((e & k) == 0);
            bool sw = up ? (a < c) : (a > c);
            if (sw) { keys[e] = c; keys[f] = a; }
            __syncthreads();
        }
    if (tid < KSEL) sel[tid] = Tn - 1 - (int)(keys[tid] & 0xffffffffull);
    __syncthreads();
    for (int k = 2; k <= KSEL; k <<= 1)
        for (int j = k >> 1; j > 0; j >>= 1) {
            if (tid < KSEL/2) {
                int p = tid;
                int e = ((p & ~(j - 1)) << 1) | (p & (j - 1));
                int f = e | j;
                int a = sel[e], c = sel[f];
                bool up = ((e & k) == 0);
                bool sw = up ? (a > c) : (a < c);
                if (sw) { sel[e] = c; sel[f] = a; }
            }
            __syncthreads();
        }
    if (tid < KSEL) g_idx[b*KSEL + tid] = sel[tid];
}

// ---------------- gather selected tokens -------------------------------------
__global__ __launch_bounds__(192)
void gather_kernel() {
    int bk = blockIdx.x;
    int b = bk / KSEL;
    int t = g_idx[bk];
    if (threadIdx.x == 0) {
        g_gsel[bk] = g_energy[b*Tn + t];
        g_selmap[b*Tn + t] = bk % KSEL;
    }
    const float4* src = (const float4*)(g_hrnn + ((size_t)b*Tn + t) * Cn);
    float4* dst = (float4*)(g_xsel + (size_t)bk * Cn);
    dst[threadIdx.x] = src[threadIdx.x];
}

// ---------------- flash attention (causal, hd=64, Klen=1024) -----------------
__global__ __launch_bounds__(256)
void attn_kernel() {
    extern __shared__ float sm[];
    float* Qs = sm;
    float* Ks = Qs + 64*65;
    float* Ps = Ks + 64*65;
    float* Vs = Ps + 64*65;
    int qt = blockIdx.x, bh = blockIdx.y;
    int b = bh / Hn, h = bh % Hn;
    int tid = threadIdx.x, tr = tid >> 4, tc = tid & 15;
    int q0 = qt * 64;
    const float* base = g_qkv + (size_t)b * KSEL * G3C;

    for (int i = tid; i < 1024; i += 256) {
        int r = i >> 4, d4 = i & 15;
        float4 v = __ldg((const float4*)(base + (size_t)(q0 + r)*G3C + h*64) + d4);
        Qs[r*65 + d4*4 + 0] = v.x; Qs[r*65 + d4*4 + 1] = v.y;
        Qs[r*65 + d4*4 + 2] = v.z; Qs[r*65 + d4*4 + 3] = v.w;
    }

    ull op[4][2];
    float m[4], l[4];
#pragma unroll
    for (int i = 0; i < 4; i++) {
        m[i] = -1e30f; l[i] = 0.f;
        op[i][0] = 0ull; op[i][1] = 0ull;
    }

    for (int kt = 0; kt <= qt; kt++) {
        int k0 = kt * 64;
        for (int i = tid; i < 1024; i += 256) {
            int c = i >> 4, d4 = i & 15;
            float4 kv = __ldg((const float4*)(base + (size_t)(k0 + c)*G3C + Cn + h*64) + d4);
            Ks[c*65 + d4*4 + 0] = kv.x; Ks[c*65 + d4*4 + 1] = kv.y;
            Ks[c*65 + d4*4 + 2] = kv.z; Ks[c*65 + d4*4 + 3] = kv.w;
            float4 vv = __ldg((const float4*)(base + (size_t)(k0 + c)*G3C + 2*Cn + h*64) + d4);
            ((float4*)(Vs + c*64))[d4] = vv;
        }
        __syncthreads();

        ull sp[4][2];
#pragma unroll
        for (int i = 0; i < 4; i++) { sp[i][0] = 0ull; sp[i][1] = 0ull; }
        for (int kk = 0; kk < 64; kk++) {
            ull ad[4], bp[2];
#pragma unroll
            for (int i = 0; i < 4; i++) ad[i] = dup2(Qs[(tr*4 + i)*65 + kk]);
            {
                float bb0 = Ks[(tc*4 + 0)*65 + kk];
                float bb1 = Ks[(tc*4 + 1)*65 + kk];
                float bb2 = Ks[(tc*4 + 2)*65 + kk];
                float bb3 = Ks[(tc*4 + 3)*65 + kk];
                bp[0] = pk2(bb0, bb1); bp[1] = pk2(bb2, bb3);
            }
#pragma unroll
            for (int i = 0; i < 4; i++) {
                fma2(sp[i][0], ad[i], bp[0]);
                fma2(sp[i][1], ad[i], bp[1]);
            }
        }
        float s[4][4];
#pragma unroll
        for (int i = 0; i < 4; i++) {
            float2 p0 = upk2(sp[i][0]), p1 = upk2(sp[i][1]);
            s[i][0] = p0.x * 0.125f; s[i][1] = p0.y * 0.125f;
            s[i][2] = p1.x * 0.125f; s[i][3] = p1.y * 0.125f;
        }
        if (kt == qt) {
#pragma unroll
            for (int i = 0; i < 4; i++)
#pragma unroll
                for (int j = 0; j < 4; j++)
                    if (k0 + tc*4 + j > q0 + tr*4 + i) s[i][j] = -1e30f;
        }
#pragma unroll
        for (int i = 0; i < 4; i++) {
            float rm = s[i][0];
#pragma unroll
            for (int j = 1; j < 4; j++) rm = fmaxf(rm, s[i][j]);
#pragma unroll
            for (int off = 8; off > 0; off >>= 1)
                rm = fmaxf(rm, __shfl_xor_sync(0xffffffffu, rm, off));
            float mn = fmaxf(m[i], rm);
            float alpha = expf(m[i] - mn);
            float rs = 0.f;
#pragma unroll
            for (int j = 0; j < 4; j++) {
                s[i][j] = expf(s[i][j] - mn);
                rs += s[i][j];
            }
#pragma unroll
            for (int off = 8; off > 0; off >>= 1)
                rs += __shfl_xor_sync(0xffffffffu, rs, off);
            l[i] = l[i] * alpha + rs;
            m[i] = mn;
            ull da = dup2(alpha);
            op[i][0] = mul2(op[i][0], da);
            op[i][1] = mul2(op[i][1], da);
#pragma unroll
            for (int j = 0; j < 4; j++) Ps[(tr*4 + i)*65 + tc*4 + j] = s[i][j];
        }
        __syncthreads();
        for (int c = 0; c < 64; c++) {
            ull pd[4], vp[2];
#pragma unroll
            for (int i = 0; i < 4; i++) pd[i] = dup2(Ps[(tr*4 + i)*65 + c]);
            {
                float4 vv = *(const float4*)(Vs + c*64 + tc*4);
                vp[0] = pk2(vv.x, vv.y); vp[1] = pk2(vv.z, vv.w);
            }
#pragma unroll
            for (int i = 0; i < 4; i++) {
                fma2(op[i][0], pd[i], vp[0]);
                fma2(op[i][1], pd[i], vp[1]);
            }
        }
        __syncthreads();
    }
#pragma unroll
    for (int i = 0; i < 4; i++) {
        float inv = 1.f / l[i];
        int row = b * KSEL + q0 + tr*4 + i;
        float2 p0 = upk2(op[i][0]), p1 = upk2(op[i][1]);
        float* dst = g_y + (size_t)row * Cn + h*64 + tc*4;
        dst[0] = p0.x * inv; dst[1] = p0.y * inv;
        dst[2] = p1.x * inv; dst[3] = p1.y * inv;
    }
}

// ---------------- LayerNorm with fused scatter-add ---------------------------
__global__ __launch_bounds__(256)
void ln_kernel(const float* __restrict__ g, const float* __restrict__ bb) {
    __shared__ float xrow[Cn];
    __shared__ float rbuf[16];
    int tok = blockIdx.x, tid = threadIdx.x;
    int b = tok >> 11;
    int sel = g_selmap[tok];
    float s = 0.f, s2 = 0.f;
    for (int c = tid; c < Cn; c += 256) {
        float v = g_hrnn[(size_t)tok*Cn + c];
        if (sel >= 0) v += g_weighted[((size_t)(b*KSEL + sel))*Cn + c];
        xrow[c] = v; s += v; s2 += v*v;
    }
#pragma unroll
    for (int off = 16; off > 0; off >>= 1) {
        s  += __shfl_xor_sync(0xffffffffu, s, off);
        s2 += __shfl_xor_sync(0xffffffffu, s2, off);
    }
    int w = tid >> 5;
    if ((tid & 31) == 0) { rbuf[w] = s; rbuf[8 + w] = s2; }
    __syncthreads();
    if (tid == 0) {
        float S = 0.f, S2 = 0.f;
        for (int i = 0; i < 8; i++) { S += rbuf[i]; S2 += rbuf[8 + i]; }
        float mu = S / (float)Cn;
        float var = S2 / (float)Cn - mu*mu;
        rbuf[0] = mu; rbuf[1] = rsqrtf(var + 1e-5f);
    }
    __syncthreads();
    float mu = rbuf[0], inv = rbuf[1];
    for (int c = tid; c < Cn; c += 256)
        g_hln[(size_t)tok*Cn + c] = (xrow[c] - mu) * inv * g[c] + bb[c];
}

// ---------------- finalize ----------------------------------------------------
__global__ void finalize_kernel(float* out) {
    out[(size_t)BT*Cn + BT] = (float)g_active;
}

// ---------------- launcher ----------------------------------------------------
extern "C" void kernel_launch(void* const* d_in, const int* in_sizes, int n_in,
                              void* d_out, int out_size) {
    const float* x      = (const float*)d_in[0];
    const float* W_ih   = (const float*)d_in[1];
    const float* W_hh   = (const float*)d_in[2];
    const float* b_ih   = (const float*)d_in[3];
    const float* b_hh   = (const float*)d_in[4];
    const float* gate_w1= (const float*)d_in[5];
    const float* gate_b1= (const float*)d_in[6];
    const float* gate_w2= (const float*)d_in[7];
    const float* gate_b2= (const float*)d_in[8];
    const float* qkv_w  = (const float*)d_in[9];
    const float* qkv_b  = (const float*)d_in[10];
    const float* proj_w = (const float*)d_in[11];
    const float* proj_b = (const float*)d_in[12];
    const float* ln_g   = (const float*)d_in[13];
    const float* ln_b   = (const float*)d_in[14];
    const float* ffn_w1 = (const float*)d_in[15];
    const float* ffn_b1 = (const float*)d_in[16];
    const float* ffn_w2 = (const float*)d_in[17];
    const float* ffn_b2 = (const float*)d_in[18];
    float* out = (float*)d_out;

    float *p_xi, *p_xsel, *p_qkv, *p_y, *p_weighted, *p_hln, *p_mid, *p_energy_out;
    cudaGetSymbolAddress((void**)&p_xi,       g_xi);
    cudaGetSymbolAddress((void**)&p_xsel,     g_xsel);
    cudaGetSymbolAddress((void**)&p_qkv,      g_qkv);
    cudaGetSymbolAddress((void**)&p_y,        g_y);
    cudaGetSymbolAddress((void**)&p_weighted, g_weighted);
    cudaGetSymbolAddress((void**)&p_hln,      g_hln);
    cudaGetSymbolAddress((void**)&p_mid,      g_mid);
    float* p_gsel; cudaGetSymbolAddress((void**)&p_gsel, g_gsel);
    p_energy_out = out + (size_t)BT*Cn;

    const int ATTN_SMEM = (3*64*65 + 64*64) * 4;
    cudaFuncSetAttribute(attn_kernel, cudaFuncAttributeMaxDynamicSharedMemorySize, ATTN_SMEM);

    // 0) init scratch state
    init_kernel<<<64, 256>>>();

    // 1) xi = x @ W_ih^T + b_ih   (fp32 FFMA — precision-critical path)
    gemm_kernel<<<dim3(G3C/128, BT/128), 256>>>(x, W_ih, b_ih, nullptr, p_xi, BT, G3C, Cn);

    // 2) GRU scan (persistent, global barrier per step)
    gru_kernel<<<NCTA_GRU, 192>>>(p_xi, W_hh, b_hh);

    // 3) gate MLP energy
    energy_kernel<<<BT, 128>>>(gate_w1, gate_b1, gate_w2, gate_b2, p_energy_out);

    // 4) exact top-k + ascending index sort
    topk_kernel<<<Bn, 1024>>>();

    // 5) gather selected tokens
    gather_kernel<<<BKn, 192>>>();

    // 6) qkv = x_sel @ qkv_w^T + qkv_b  (TF32 tensor cores)
    gemm_tc_kernel<0><<<dim3(G3C/128, BKn/128), 256>>>(p_xsel, qkv_w, qkv_b, nullptr, p_qkv, BKn, G3C, Cn);

    // 7) causal flash attention
    attn_kernel<<<dim3(KSEL/64, Bn*Hn), 256, ATTN_SMEM>>>();

    // 8) weighted = (y @ proj_w^T + proj_b) * g_sel  (TF32)
    gemm_tc_kernel<2><<<dim3(Cn/128, BKn/128), 256>>>(p_y, proj_w, proj_b, p_gsel, p_weighted, BKn, Cn, Cn);

    // 9) LayerNorm(h_rnn + scatter(weighted))
    ln_kernel<<<BT, 256>>>(ln_g, ln_b);

    // 10) mid = gelu(h_ln @ ffn_w1^T + ffn_b1)  (TF32)
    gemm_tc_kernel<1><<<dim3(DFF/128, BT/128), 256>>>(p_hln, ffn_w1, ffn_b1, nullptr, p_mid, BT, DFF, Cn);

    // 11) out_h = h_ln + mid @ ffn_w2^T + ffn_b2  (TF32) -> d_out
    gemm_tc_kernel<3><<<dim3(Cn/128, BT/128), 256>>>(p_mid, ffn_w2, ffn_b2, p_hln, out, BT, Cn, DFF);

    // 12) active count
    finalize_kernel<<<1, 1>>>(out);

    (void)in_sizes; (void)n_in; (void)out_size;
}